// round 1
// baseline (speedup 1.0000x reference)
#include <cuda_runtime.h>
#include <cuda_bf16.h>

// ---------------------------------------------------------------------------
// Problem shape (fixed): bs=2, seq=2048, embed=1024, heads=16, head_dim=64
//   x      [2, 2048, 1024]  f32
//   w_qkv  [3072, 1024]     f32   (torch layout: [out_features, in_features])
//   w_out  [1024, 1024]     f32
//   b_out  [1024]           f32
//   out    [2, 2048, 1024]  f32
// Pipeline: QKV GEMM -> causal flash attention -> out GEMM (+bias)
// ---------------------------------------------------------------------------

#define SEQ   2048
#define EMB   1024
#define NH    16
#define HD    64
#define ROWS  4096          // bs * seq

// Scratch (allocation-free rule: __device__ globals)
__device__ float g_qkv[(size_t)ROWS * 3 * EMB];   // [4096, 3072]
__device__ float g_att[(size_t)ROWS * EMB];       // [4096, 1024]

// ---------------------------------------------------------------------------
// SGEMM: C[M,N] = A[M,K] @ B[N,K]^T (+bias[n]).  BM=BN=128, BK=16, 256 thr,
// 8x8 register micro-tile. M,N,K multiples of 128/16 (true for both uses).
// ---------------------------------------------------------------------------
template<bool BIAS>
__global__ __launch_bounds__(256)
void sgemm_nt(const float* __restrict__ A, const float* __restrict__ B,
              const float* __restrict__ bias, float* __restrict__ C,
              int M, int N, int K)
{
    __shared__ float As[16][132];
    __shared__ float Bs[16][132];

    const int tid = threadIdx.x;
    const int tx  = tid & 15;      // 0..15 -> N micro
    const int ty  = tid >> 4;      // 0..15 -> M micro
    const int bm  = blockIdx.y * 128;
    const int bn  = blockIdx.x * 128;

    float acc[8][8];
    #pragma unroll
    for (int i = 0; i < 8; i++)
        #pragma unroll
        for (int j = 0; j < 8; j++) acc[i][j] = 0.f;

    const int lr = tid >> 2;           // 0..63
    const int lc = (tid & 3) << 2;     // 0,4,8,12
    const float* Ab = A + (size_t)bm * K;
    const float* Bb = B + (size_t)bn * K;

    for (int k0 = 0; k0 < K; k0 += 16) {
        #pragma unroll
        for (int it = 0; it < 2; it++) {
            int r = lr + it * 64;
            float4 va = *(const float4*)(Ab + (size_t)r * K + k0 + lc);
            As[lc + 0][r] = va.x; As[lc + 1][r] = va.y;
            As[lc + 2][r] = va.z; As[lc + 3][r] = va.w;
            float4 vb = *(const float4*)(Bb + (size_t)r * K + k0 + lc);
            Bs[lc + 0][r] = vb.x; Bs[lc + 1][r] = vb.y;
            Bs[lc + 2][r] = vb.z; Bs[lc + 3][r] = vb.w;
        }
        __syncthreads();
        #pragma unroll
        for (int k = 0; k < 16; k++) {
            float a[8], b[8];
            *(float4*)(a)     = *(const float4*)&As[k][ty * 8];
            *(float4*)(a + 4) = *(const float4*)&As[k][ty * 8 + 4];
            *(float4*)(b)     = *(const float4*)&Bs[k][tx * 8];
            *(float4*)(b + 4) = *(const float4*)&Bs[k][tx * 8 + 4];
            #pragma unroll
            for (int i = 0; i < 8; i++)
                #pragma unroll
                for (int j = 0; j < 8; j++)
                    acc[i][j] += a[i] * b[j];
        }
        __syncthreads();
    }

    #pragma unroll
    for (int i = 0; i < 8; i++) {
        int row = bm + ty * 8 + i;
        int col = bn + tx * 8;
        float4 o0 = make_float4(acc[i][0], acc[i][1], acc[i][2], acc[i][3]);
        float4 o1 = make_float4(acc[i][4], acc[i][5], acc[i][6], acc[i][7]);
        if (BIAS) {
            float4 b0 = *(const float4*)(bias + col);
            float4 b1 = *(const float4*)(bias + col + 4);
            o0.x += b0.x; o0.y += b0.y; o0.z += b0.z; o0.w += b0.w;
            o1.x += b1.x; o1.y += b1.y; o1.z += b1.z; o1.w += b1.w;
        }
        *(float4*)(C + (size_t)row * N + col)     = o0;
        *(float4*)(C + (size_t)row * N + col + 4) = o1;
    }
}

// ---------------------------------------------------------------------------
// Causal flash attention.
// Grid: (qblocks=16, heads=16, batch=2), 256 threads.
// Per CTA: 128 query rows, iterate key blocks of 64 (only j <= row blocks).
// GEMM1 (S=Q K^T) and GEMM2 (O += P V) are register-tiled 8x4 per thread
// (ty -> 8 rows, tx -> 4 cols). Online softmax state (m,l) lives per-thread,
// replicated across the 16 tx lanes of each row group; row reductions via
// __shfl_xor over lanes {1,2,4,8} (stays within the 16-lane tx group).
// P staged through smem transposed for the PV GEMM.
// qkv layout: row-major [4096, 3072], head h occupies cols [h*192, h*192+192)
// with q at +0, k at +64, v at +128.
// ---------------------------------------------------------------------------
#define QT_S 132
#define KT_S 68
#define VS_S 68
#define PT_S 132
#define ATT_SMEM ((64 * QT_S + 64 * KT_S + 64 * VS_S + 64 * PT_S) * 4)

__global__ __launch_bounds__(256, 2)
void attn_kernel(const float* __restrict__ qkv, float* __restrict__ out)
{
    extern __shared__ float sm[];
    float* Qt = sm;                  // [64][132]  Q transposed: Qt[d][row]
    float* Kt = Qt + 64 * QT_S;      // [64][68]   K transposed: Kt[d][j]
    float* Vs = Kt + 64 * KT_S;      // [64][68]   V natural:    Vs[j][d]
    float* Pt = Vs + 64 * VS_S;      // [64][132]  P transposed: Pt[j][row]

    const int tid = threadIdx.x;
    const int tx  = tid & 15;    // 0..15 -> 4 cols (j of S, d of O)
    const int ty  = tid >> 4;    // 0..15 -> 8 rows
    const int qb  = blockIdx.x;  // 0..15
    const int h   = blockIdx.y;  // 0..15
    const int b   = blockIdx.z;  // 0..1
    const size_t base = (size_t)b * SEQ * 3072;

    // Load Q tile [128][64] transposed into Qt
    #pragma unroll
    for (int p = 0; p < 8; p++) {
        int r = ty + p * 16;
        int d = tx * 4;
        float4 v = *(const float4*)(qkv + base + (size_t)(qb * 128 + r) * 3072 + h * 192 + d);
        Qt[(d + 0) * QT_S + r] = v.x;
        Qt[(d + 1) * QT_S + r] = v.y;
        Qt[(d + 2) * QT_S + r] = v.z;
        Qt[(d + 3) * QT_S + r] = v.w;
    }

    float m[8], l[8], acc[8][4];
    #pragma unroll
    for (int i = 0; i < 8; i++) {
        m[i] = -1e30f; l[i] = 0.f;
        #pragma unroll
        for (int j = 0; j < 4; j++) acc[i][j] = 0.f;
    }

    const int row0 = qb * 128 + ty * 8;
    const int nblocks = (qb + 1) * 2;   // causal: key blocks up to the diagonal

    for (int kb = 0; kb < nblocks; kb++) {
        const int j0 = kb * 64;
        __syncthreads();   // previous iteration's Kt/Vs/Pt reads done
        // Load K (transposed) and V (natural) tiles
        #pragma unroll
        for (int p = 0; p < 4; p++) {
            int j = ty + p * 16;
            int d = tx * 4;
            const float* rowp = qkv + base + (size_t)(j0 + j) * 3072 + h * 192;
            float4 kv = *(const float4*)(rowp + 64 + d);
            Kt[(d + 0) * KT_S + j] = kv.x;
            Kt[(d + 1) * KT_S + j] = kv.y;
            Kt[(d + 2) * KT_S + j] = kv.z;
            Kt[(d + 3) * KT_S + j] = kv.w;
            float4 vv = *(const float4*)(rowp + 128 + d);
            *(float4*)&Vs[j * VS_S + d] = vv;
        }
        __syncthreads();

        // GEMM1: S[128][64] = Q @ K^T
        float s[8][4];
        #pragma unroll
        for (int i = 0; i < 8; i++)
            #pragma unroll
            for (int j = 0; j < 4; j++) s[i][j] = 0.f;
        #pragma unroll 16
        for (int d = 0; d < 64; d++) {
            float a[8], bk[4];
            *(float4*)(a)     = *(const float4*)&Qt[d * QT_S + ty * 8];
            *(float4*)(a + 4) = *(const float4*)&Qt[d * QT_S + ty * 8 + 4];
            *(float4*)(bk)    = *(const float4*)&Kt[d * KT_S + tx * 4];
            #pragma unroll
            for (int i = 0; i < 8; i++)
                #pragma unroll
                for (int j = 0; j < 4; j++)
                    s[i][j] += a[i] * bk[j];
        }

        // Causal mask + softmax scale (1/sqrt(64) = 0.125)
        const int col0 = j0 + tx * 4;
        #pragma unroll
        for (int i = 0; i < 8; i++)
            #pragma unroll
            for (int j = 0; j < 4; j++)
                s[i][j] = (col0 + j > row0 + i) ? -1e30f : s[i][j] * 0.125f;

        // Online softmax: row reductions across the 16 tx lanes
        float rescale[8];
        #pragma unroll
        for (int i = 0; i < 8; i++) {
            float mx = fmaxf(fmaxf(s[i][0], s[i][1]), fmaxf(s[i][2], s[i][3]));
            mx = fmaxf(mx, __shfl_xor_sync(0xffffffffu, mx, 1));
            mx = fmaxf(mx, __shfl_xor_sync(0xffffffffu, mx, 2));
            mx = fmaxf(mx, __shfl_xor_sync(0xffffffffu, mx, 4));
            mx = fmaxf(mx, __shfl_xor_sync(0xffffffffu, mx, 8));
            float mn = fmaxf(m[i], mx);
            rescale[i] = __expf(m[i] - mn);
            m[i] = mn;
            float rs = 0.f;
            #pragma unroll
            for (int j = 0; j < 4; j++) {
                float p = __expf(s[i][j] - mn);
                s[i][j] = p;
                rs += p;
            }
            rs += __shfl_xor_sync(0xffffffffu, rs, 1);
            rs += __shfl_xor_sync(0xffffffffu, rs, 2);
            rs += __shfl_xor_sync(0xffffffffu, rs, 4);
            rs += __shfl_xor_sync(0xffffffffu, rs, 8);
            l[i] = l[i] * rescale[i] + rs;
        }

        // Stage P transposed; rescale running O accumulator
        #pragma unroll
        for (int i = 0; i < 8; i++) {
            #pragma unroll
            for (int j = 0; j < 4; j++)
                Pt[(tx * 4 + j) * PT_S + ty * 8 + i] = s[i][j];
            acc[i][0] *= rescale[i];
            acc[i][1] *= rescale[i];
            acc[i][2] *= rescale[i];
            acc[i][3] *= rescale[i];
        }
        __syncthreads();

        // GEMM2: O[128][64] += P @ V
        #pragma unroll 16
        for (int j = 0; j < 64; j++) {
            float a[8], bv[4];
            *(float4*)(a)     = *(const float4*)&Pt[j * PT_S + ty * 8];
            *(float4*)(a + 4) = *(const float4*)&Pt[j * PT_S + ty * 8 + 4];
            *(float4*)(bv)    = *(const float4*)&Vs[j * VS_S + tx * 4];
            #pragma unroll
            for (int i = 0; i < 8; i++)
                #pragma unroll
                for (int jd = 0; jd < 4; jd++)
                    acc[i][jd] += a[i] * bv[jd];
        }
    }

    // Epilogue: out[b, row, h*64 + d] = acc / l
    #pragma unroll
    for (int i = 0; i < 8; i++) {
        float inv = 1.f / l[i];
        int row = row0 + i;
        float4 o = make_float4(acc[i][0] * inv, acc[i][1] * inv,
                               acc[i][2] * inv, acc[i][3] * inv);
        *(float4*)(out + ((size_t)b * SEQ + row) * EMB + h * HD + tx * 4) = o;
    }
}

// ---------------------------------------------------------------------------
extern "C" void kernel_launch(void* const* d_in, const int* in_sizes, int n_in,
                              void* d_out, int out_size)
{
    const float* x    = (const float*)d_in[0];   // [2,2048,1024]
    const float* wqkv = (const float*)d_in[1];   // [3072,1024]
    const float* wout = (const float*)d_in[2];   // [1024,1024]
    const float* bout = (const float*)d_in[3];   // [1024]
    float* out = (float*)d_out;

    float *qkv, *att;
    cudaGetSymbolAddress((void**)&qkv, g_qkv);
    cudaGetSymbolAddress((void**)&att, g_att);
    cudaFuncSetAttribute(attn_kernel,
                         cudaFuncAttributeMaxDynamicSharedMemorySize, ATT_SMEM);

    // 1) QKV projection: [4096,3072] = x[4096,1024] @ w_qkv[3072,1024]^T
    sgemm_nt<false><<<dim3(3072 / 128, ROWS / 128), 256>>>(
        x, wqkv, nullptr, qkv, ROWS, 3072, EMB);

    // 2) Causal attention -> [4096,1024]
    attn_kernel<<<dim3(SEQ / 128, NH, 2), 256, ATT_SMEM>>>(qkv, att);

    // 3) Output projection + bias
    sgemm_nt<true><<<dim3(EMB / 128, ROWS / 128), 256>>>(
        att, wout, bout, out, ROWS, EMB, EMB);
}

// round 4
// speedup vs baseline: 1.5421x; 1.5421x over previous
#include <cuda_runtime.h>
#include <cuda_bf16.h>
#include <cstdint>

// ---------------------------------------------------------------------------
// bs=2, seq=2048, embed=1024, heads=16, head_dim=64
//   x[2,2048,1024] @ w_qkv[3072,1024]^T -> qkv ; flash attn ; @ w_out^T + b
// GEMMs: bf16 mma.sync (m16n8k16) with 3-term hi/lo split (fp32-accurate).
// Attention: fp32 register-tiled flash attention.
// ---------------------------------------------------------------------------

#define SEQ   2048
#define EMB   1024
#define NH    16
#define HD    64
#define ROWS  4096

__device__ float          g_qkv[(size_t)ROWS * 3 * EMB];
__device__ float          g_att[(size_t)ROWS * EMB];
__device__ __nv_bfloat16  g_xh [(size_t)ROWS * EMB];
__device__ __nv_bfloat16  g_xl [(size_t)ROWS * EMB];
__device__ __nv_bfloat16  g_wqh[(size_t)3 * EMB * EMB];
__device__ __nv_bfloat16  g_wql[(size_t)3 * EMB * EMB];
__device__ __nv_bfloat16  g_ath[(size_t)ROWS * EMB];
__device__ __nv_bfloat16  g_atl[(size_t)ROWS * EMB];
__device__ __nv_bfloat16  g_woh[(size_t)EMB * EMB];
__device__ __nv_bfloat16  g_wol[(size_t)EMB * EMB];

// ---------------------------------------------------------------------------
__device__ __forceinline__ uint32_t smem_u32(const void* p) {
    uint32_t a;
    asm("{ .reg .u64 t; cvta.to.shared.u64 t, %1; cvt.u32.u64 %0, t; }"
        : "=r"(a) : "l"(p));
    return a;
}

__device__ __forceinline__ void cp_async16(uint32_t dst, const void* src) {
    asm volatile("cp.async.cg.shared.global [%0], [%1], 16;"
                 :: "r"(dst), "l"(src));
}
__device__ __forceinline__ void cp_commit() {
    asm volatile("cp.async.commit_group;");
}
template<int N>
__device__ __forceinline__ void cp_wait() {
    asm volatile("cp.async.wait_group %0;" :: "n"(N));
}

__device__ __forceinline__ void ldsm_x4(uint32_t* r, uint32_t addr) {
    asm volatile("ldmatrix.sync.aligned.m8n8.x4.shared.b16 {%0,%1,%2,%3}, [%4];"
                 : "=r"(r[0]), "=r"(r[1]), "=r"(r[2]), "=r"(r[3]) : "r"(addr));
}

__device__ __forceinline__ void mma16816(float* d, const uint32_t* a,
                                         const uint32_t* b) {
    asm volatile(
        "mma.sync.aligned.m16n8k16.row.col.f32.bf16.bf16.f32 "
        "{%0,%1,%2,%3}, {%4,%5,%6,%7}, {%8,%9}, {%0,%1,%2,%3};"
        : "+f"(d[0]), "+f"(d[1]), "+f"(d[2]), "+f"(d[3])
        : "r"(a[0]), "r"(a[1]), "r"(a[2]), "r"(a[3]), "r"(b[0]), "r"(b[1]));
}

// ---------------------------------------------------------------------------
// fp32 -> bf16 (hi, lo) split
// ---------------------------------------------------------------------------
__global__ __launch_bounds__(256)
void split_bf16(const float* __restrict__ in,
                __nv_bfloat16* __restrict__ hi,
                __nv_bfloat16* __restrict__ lo, int n)
{
    int i = (blockIdx.x * 256 + threadIdx.x) * 4;
    if (i >= n) return;
    float4 v = *(const float4*)(in + i);
    __nv_bfloat16 h0 = __float2bfloat16(v.x);
    __nv_bfloat16 h1 = __float2bfloat16(v.y);
    __nv_bfloat16 h2 = __float2bfloat16(v.z);
    __nv_bfloat16 h3 = __float2bfloat16(v.w);
    __nv_bfloat16 l0 = __float2bfloat16(v.x - __bfloat162float(h0));
    __nv_bfloat16 l1 = __float2bfloat16(v.y - __bfloat162float(h1));
    __nv_bfloat16 l2 = __float2bfloat16(v.z - __bfloat162float(h2));
    __nv_bfloat16 l3 = __float2bfloat16(v.w - __bfloat162float(h3));
    __nv_bfloat162 hp0 = {h0, h1}, hp1 = {h2, h3};
    __nv_bfloat162 lp0 = {l0, l1}, lp1 = {l2, l3};
    *(__nv_bfloat162*)(hi + i)     = hp0;
    *(__nv_bfloat162*)(hi + i + 2) = hp1;
    *(__nv_bfloat162*)(lo + i)     = lp0;
    *(__nv_bfloat162*)(lo + i + 2) = lp1;
}

// ---------------------------------------------------------------------------
// bf16 split GEMM via mma.sync: C[M,N] = A[M,K] @ B[N,K]^T (+bias)
//   C = Ah Bh^T + Ah Bl^T + Al Bh^T
// CTA 128x128xBK32, 256 threads (8 warps = 2x4 of 64x32 warp tiles),
// cp.async double buffering, padded smem (stride 40 bf16) for ldmatrix.
// ---------------------------------------------------------------------------
#define STRD   40                       // bf16 elements per smem row
#define TILE_B (128 * STRD * 2)         // 10240 bytes per tile
#define BUF_B  (4 * TILE_B)             // Ah, Al, Bh, Bl
#define GSMEM  (2 * BUF_B)              // 81920 bytes

template<bool BIAS>
__global__ __launch_bounds__(256)
void gemm_mma(const __nv_bfloat16* __restrict__ Ah, const __nv_bfloat16* __restrict__ Al,
              const __nv_bfloat16* __restrict__ Bh, const __nv_bfloat16* __restrict__ Bl,
              const float* __restrict__ bias, float* __restrict__ C,
              int M, int N, int K)
{
    extern __shared__ char smem[];
    const uint32_t sbase = smem_u32(smem);

    const int t    = threadIdx.x;
    const int warp = t >> 5;
    const int lane = t & 31;
    const int wm   = warp >> 2;          // 0..1  -> m offset *64
    const int wn   = warp & 3;           // 0..3  -> n offset *32
    const int bm   = blockIdx.y * 128;
    const int bn   = blockIdx.x * 128;

    // ldmatrix coords
    const int aRow = (lane & 15);
    const int aKh  = lane >> 4;                       // 0/1 -> k+8
    const int bN   = ((lane >> 4) << 3) + (lane & 7); // n row within 16
    const int bKh  = (lane >> 3) & 1;                 // 0/1 -> k+8

    float acc[4][4][4];
    #pragma unroll
    for (int i = 0; i < 4; i++)
        #pragma unroll
        for (int j = 0; j < 4; j++)
            #pragma unroll
            for (int r = 0; r < 4; r++) acc[i][j][r] = 0.f;

    const int nck = K >> 5;

    // Full tile: 128 rows x 32 k-elements = 512 x 16B per tile.
    // 256 threads x 2 iters x 16B covers it.
    auto load_chunk = [&](int ck, int buf) {
        const int k0 = ck << 5;
        #pragma unroll
        for (int it = 0; it < 2; it++) {
            const int linear = it * 256 + t;
            const int row = linear >> 2;           // 0..127
            const int kc  = (linear & 3) << 3;     // 0,8,16,24 elements
            uint32_t d = sbase + buf * BUF_B + (row * STRD + kc) * 2;
            const size_t goA = (size_t)(bm + row) * K + k0 + kc;
            const size_t goB = (size_t)(bn + row) * K + k0 + kc;
            cp_async16(d,              Ah + goA);
            cp_async16(d + TILE_B,     Al + goA);
            cp_async16(d + 2 * TILE_B, Bh + goB);
            cp_async16(d + 3 * TILE_B, Bl + goB);
        }
    };

    load_chunk(0, 0);
    cp_commit();

    for (int ck = 0; ck < nck; ck++) {
        const int buf = ck & 1;
        if (ck + 1 < nck) { load_chunk(ck + 1, buf ^ 1); cp_commit(); cp_wait<1>(); }
        else              { cp_wait<0>(); }
        __syncthreads();

        const uint32_t bu  = sbase + buf * BUF_B;
        const uint32_t ahs = bu;
        const uint32_t als = bu + TILE_B;
        const uint32_t bhs = bu + 2 * TILE_B;
        const uint32_t bls = bu + 3 * TILE_B;

        #pragma unroll
        for (int ks = 0; ks < 2; ks++) {
            const int k0 = ks * 16;
            uint32_t ah[4][4], al[4][4], bh[4][2], bl[4][2];
            #pragma unroll
            for (int mi = 0; mi < 4; mi++) {
                uint32_t off = ((wm * 64 + mi * 16 + aRow) * STRD + k0 + aKh * 8) * 2;
                ldsm_x4(ah[mi], ahs + off);
                ldsm_x4(al[mi], als + off);
            }
            #pragma unroll
            for (int p = 0; p < 2; p++) {
                uint32_t off = ((wn * 32 + p * 16 + bN) * STRD + k0 + bKh * 8) * 2;
                uint32_t rh[4], rl[4];
                ldsm_x4(rh, bhs + off);
                ldsm_x4(rl, bls + off);
                bh[p * 2][0] = rh[0]; bh[p * 2][1] = rh[1];
                bh[p * 2 + 1][0] = rh[2]; bh[p * 2 + 1][1] = rh[3];
                bl[p * 2][0] = rl[0]; bl[p * 2][1] = rl[1];
                bl[p * 2 + 1][0] = rl[2]; bl[p * 2 + 1][1] = rl[3];
            }
            #pragma unroll
            for (int mi = 0; mi < 4; mi++)
                #pragma unroll
                for (int nj = 0; nj < 4; nj++) {
                    mma16816(acc[mi][nj], ah[mi], bh[nj]);
                    mma16816(acc[mi][nj], ah[mi], bl[nj]);
                    mma16816(acc[mi][nj], al[mi], bh[nj]);
                }
        }
        __syncthreads();
    }

    // epilogue
    const int r0 = bm + wm * 64 + (lane >> 2);
    const int c0 = bn + wn * 32 + (lane & 3) * 2;
    #pragma unroll
    for (int mi = 0; mi < 4; mi++)
        #pragma unroll
        for (int nj = 0; nj < 4; nj++) {
            int row = r0 + mi * 16;
            int col = c0 + nj * 8;
            float2 v0 = make_float2(acc[mi][nj][0], acc[mi][nj][1]);
            float2 v1 = make_float2(acc[mi][nj][2], acc[mi][nj][3]);
            if (BIAS) {
                v0.x += bias[col];     v0.y += bias[col + 1];
                v1.x += bias[col];     v1.y += bias[col + 1];
            }
            *(float2*)(C + (size_t)row * N + col)       = v0;
            *(float2*)(C + (size_t)(row + 8) * N + col) = v1;
        }
}

// ---------------------------------------------------------------------------
// Causal flash attention (fp32) — unchanged.
// ---------------------------------------------------------------------------
#define QT_S 132
#define KT_S 68
#define VS_S 68
#define PT_S 132
#define ATT_SMEM ((64 * QT_S + 64 * KT_S + 64 * VS_S + 64 * PT_S) * 4)

__global__ __launch_bounds__(256, 2)
void attn_kernel(const float* __restrict__ qkv, float* __restrict__ out)
{
    extern __shared__ float sm[];
    float* Qt = sm;
    float* Kt = Qt + 64 * QT_S;
    float* Vs = Kt + 64 * KT_S;
    float* Pt = Vs + 64 * VS_S;

    const int tid = threadIdx.x;
    const int tx  = tid & 15;
    const int ty  = tid >> 4;
    const int qb  = blockIdx.x;
    const int h   = blockIdx.y;
    const int b   = blockIdx.z;
    const size_t base = (size_t)b * SEQ * 3072;

    #pragma unroll
    for (int p = 0; p < 8; p++) {
        int r = ty + p * 16;
        int d = tx * 4;
        float4 v = *(const float4*)(qkv + base + (size_t)(qb * 128 + r) * 3072 + h * 192 + d);
        Qt[(d + 0) * QT_S + r] = v.x;
        Qt[(d + 1) * QT_S + r] = v.y;
        Qt[(d + 2) * QT_S + r] = v.z;
        Qt[(d + 3) * QT_S + r] = v.w;
    }

    float m[8], l[8], acc[8][4];
    #pragma unroll
    for (int i = 0; i < 8; i++) {
        m[i] = -1e30f; l[i] = 0.f;
        #pragma unroll
        for (int j = 0; j < 4; j++) acc[i][j] = 0.f;
    }

    const int row0 = qb * 128 + ty * 8;
    const int nblocks = (qb + 1) * 2;

    for (int kb = 0; kb < nblocks; kb++) {
        const int j0 = kb * 64;
        __syncthreads();
        #pragma unroll
        for (int p = 0; p < 4; p++) {
            int j = ty + p * 16;
            int d = tx * 4;
            const float* rowp = qkv + base + (size_t)(j0 + j) * 3072 + h * 192;
            float4 kv = *(const float4*)(rowp + 64 + d);
            Kt[(d + 0) * KT_S + j] = kv.x;
            Kt[(d + 1) * KT_S + j] = kv.y;
            Kt[(d + 2) * KT_S + j] = kv.z;
            Kt[(d + 3) * KT_S + j] = kv.w;
            float4 vv = *(const float4*)(rowp + 128 + d);
            *(float4*)&Vs[j * VS_S + d] = vv;
        }
        __syncthreads();

        float s[8][4];
        #pragma unroll
        for (int i = 0; i < 8; i++)
            #pragma unroll
            for (int j = 0; j < 4; j++) s[i][j] = 0.f;
        #pragma unroll 16
        for (int d = 0; d < 64; d++) {
            float a[8], bk[4];
            *(float4*)(a)     = *(const float4*)&Qt[d * QT_S + ty * 8];
            *(float4*)(a + 4) = *(const float4*)&Qt[d * QT_S + ty * 8 + 4];
            *(float4*)(bk)    = *(const float4*)&Kt[d * KT_S + tx * 4];
            #pragma unroll
            for (int i = 0; i < 8; i++)
                #pragma unroll
                for (int j = 0; j < 4; j++)
                    s[i][j] += a[i] * bk[j];
        }

        const int col0 = j0 + tx * 4;
        #pragma unroll
        for (int i = 0; i < 8; i++)
            #pragma unroll
            for (int j = 0; j < 4; j++)
                s[i][j] = (col0 + j > row0 + i) ? -1e30f : s[i][j] * 0.125f;

        float rescale[8];
        #pragma unroll
        for (int i = 0; i < 8; i++) {
            float mx = fmaxf(fmaxf(s[i][0], s[i][1]), fmaxf(s[i][2], s[i][3]));
            mx = fmaxf(mx, __shfl_xor_sync(0xffffffffu, mx, 1));
            mx = fmaxf(mx, __shfl_xor_sync(0xffffffffu, mx, 2));
            mx = fmaxf(mx, __shfl_xor_sync(0xffffffffu, mx, 4));
            mx = fmaxf(mx, __shfl_xor_sync(0xffffffffu, mx, 8));
            float mn = fmaxf(m[i], mx);
            rescale[i] = __expf(m[i] - mn);
            m[i] = mn;
            float rs = 0.f;
            #pragma unroll
            for (int j = 0; j < 4; j++) {
                float p = __expf(s[i][j] - mn);
                s[i][j] = p;
                rs += p;
            }
            rs += __shfl_xor_sync(0xffffffffu, rs, 1);
            rs += __shfl_xor_sync(0xffffffffu, rs, 2);
            rs += __shfl_xor_sync(0xffffffffu, rs, 4);
            rs += __shfl_xor_sync(0xffffffffu, rs, 8);
            l[i] = l[i] * rescale[i] + rs;
        }

        #pragma unroll
        for (int i = 0; i < 8; i++) {
            #pragma unroll
            for (int j = 0; j < 4; j++)
                Pt[(tx * 4 + j) * PT_S + ty * 8 + i] = s[i][j];
            acc[i][0] *= rescale[i];
            acc[i][1] *= rescale[i];
            acc[i][2] *= rescale[i];
            acc[i][3] *= rescale[i];
        }
        __syncthreads();

        #pragma unroll 16
        for (int j = 0; j < 64; j++) {
            float a[8], bv[4];
            *(float4*)(a)     = *(const float4*)&Pt[j * PT_S + ty * 8];
            *(float4*)(a + 4) = *(const float4*)&Pt[j * PT_S + ty * 8 + 4];
            *(float4*)(bv)    = *(const float4*)&Vs[j * VS_S + tx * 4];
            #pragma unroll
            for (int i = 0; i < 8; i++)
                #pragma unroll
                for (int jd = 0; jd < 4; jd++)
                    acc[i][jd] += a[i] * bv[jd];
        }
    }

    #pragma unroll
    for (int i = 0; i < 8; i++) {
        float inv = 1.f / l[i];
        int row = row0 + i;
        float4 o = make_float4(acc[i][0] * inv, acc[i][1] * inv,
                               acc[i][2] * inv, acc[i][3] * inv);
        *(float4*)(out + ((size_t)b * SEQ + row) * EMB + h * HD + tx * 4) = o;
    }
}

// ---------------------------------------------------------------------------
extern "C" void kernel_launch(void* const* d_in, const int* in_sizes, int n_in,
                              void* d_out, int out_size)
{
    const float* x    = (const float*)d_in[0];
    const float* wqkv = (const float*)d_in[1];
    const float* wout = (const float*)d_in[2];
    const float* bout = (const float*)d_in[3];
    float* out = (float*)d_out;

    float *qkv, *att;
    __nv_bfloat16 *xh, *xl, *wqh, *wql, *ath, *atl, *woh, *wol;
    cudaGetSymbolAddress((void**)&qkv, g_qkv);
    cudaGetSymbolAddress((void**)&att, g_att);
    cudaGetSymbolAddress((void**)&xh,  g_xh);
    cudaGetSymbolAddress((void**)&xl,  g_xl);
    cudaGetSymbolAddress((void**)&wqh, g_wqh);
    cudaGetSymbolAddress((void**)&wql, g_wql);
    cudaGetSymbolAddress((void**)&ath, g_ath);
    cudaGetSymbolAddress((void**)&atl, g_atl);
    cudaGetSymbolAddress((void**)&woh, g_woh);
    cudaGetSymbolAddress((void**)&wol, g_wol);

    cudaFuncSetAttribute(attn_kernel,
                         cudaFuncAttributeMaxDynamicSharedMemorySize, ATT_SMEM);
    cudaFuncSetAttribute(gemm_mma<false>,
                         cudaFuncAttributeMaxDynamicSharedMemorySize, GSMEM);
    cudaFuncSetAttribute(gemm_mma<true>,
                         cudaFuncAttributeMaxDynamicSharedMemorySize, GSMEM);

    split_bf16<<<(ROWS * EMB) / 1024, 256>>>(x, xh, xl, ROWS * EMB);
    split_bf16<<<(3 * EMB * EMB) / 1024, 256>>>(wqkv, wqh, wql, 3 * EMB * EMB);
    split_bf16<<<(EMB * EMB) / 1024, 256>>>(wout, woh, wol, EMB * EMB);

    // 1) QKV projection
    gemm_mma<false><<<dim3(3072 / 128, ROWS / 128), 256, GSMEM>>>(
        xh, xl, wqh, wql, nullptr, qkv, ROWS, 3072, EMB);

    // 2) causal attention
    attn_kernel<<<dim3(SEQ / 128, NH, 2), 256, ATT_SMEM>>>(qkv, att);

    // 3) out projection + bias
    split_bf16<<<(ROWS * EMB) / 1024, 256>>>(att, ath, atl, ROWS * EMB);
    gemm_mma<true><<<dim3(EMB / 128, ROWS / 128), 256, GSMEM>>>(
        ath, atl, woh, wol, bout, out, ROWS, EMB, EMB);
}

// round 5
// speedup vs baseline: 2.7186x; 1.7629x over previous
#include <cuda_runtime.h>
#include <cuda_bf16.h>
#include <cstdint>

// ---------------------------------------------------------------------------
// bs=2, seq=2048, embed=1024, heads=16, head_dim=64
// All GEMMs (projections AND attention) on bf16 mma.sync with 3-term hi/lo
// split (fp32-level accuracy). Softmax in fp32 registers.
// ---------------------------------------------------------------------------

#define SEQ   2048
#define EMB   1024
#define NH    16
#define HD    64
#define ROWS  4096

__device__ __nv_bfloat16  g_xh  [(size_t)ROWS * EMB];
__device__ __nv_bfloat16  g_xl  [(size_t)ROWS * EMB];
__device__ __nv_bfloat16  g_wqh [(size_t)3 * EMB * EMB];
__device__ __nv_bfloat16  g_wql [(size_t)3 * EMB * EMB];
__device__ __nv_bfloat16  g_woh [(size_t)EMB * EMB];
__device__ __nv_bfloat16  g_wol [(size_t)EMB * EMB];
__device__ __nv_bfloat16  g_qkvh[(size_t)ROWS * 3 * EMB];
__device__ __nv_bfloat16  g_qkvl[(size_t)ROWS * 3 * EMB];
__device__ __nv_bfloat16  g_ath [(size_t)ROWS * EMB];
__device__ __nv_bfloat16  g_atl [(size_t)ROWS * EMB];

// ---------------------------------------------------------------------------
__device__ __forceinline__ uint32_t smem_u32(const void* p) {
    uint32_t a;
    asm("{ .reg .u64 t; cvta.to.shared.u64 t, %1; cvt.u32.u64 %0, t; }"
        : "=r"(a) : "l"(p));
    return a;
}
__device__ __forceinline__ void cp_async16(uint32_t dst, const void* src) {
    asm volatile("cp.async.cg.shared.global [%0], [%1], 16;" :: "r"(dst), "l"(src));
}
__device__ __forceinline__ void cp_commit() { asm volatile("cp.async.commit_group;"); }
template<int N>
__device__ __forceinline__ void cp_wait() {
    asm volatile("cp.async.wait_group %0;" :: "n"(N));
}
__device__ __forceinline__ void ldsm_x4(uint32_t* r, uint32_t addr) {
    asm volatile("ldmatrix.sync.aligned.m8n8.x4.shared.b16 {%0,%1,%2,%3}, [%4];"
                 : "=r"(r[0]), "=r"(r[1]), "=r"(r[2]), "=r"(r[3]) : "r"(addr));
}
__device__ __forceinline__ void ldsm_x4t(uint32_t* r, uint32_t addr) {
    asm volatile("ldmatrix.sync.aligned.m8n8.x4.trans.shared.b16 {%0,%1,%2,%3}, [%4];"
                 : "=r"(r[0]), "=r"(r[1]), "=r"(r[2]), "=r"(r[3]) : "r"(addr));
}
__device__ __forceinline__ void mma16816(float* d, const uint32_t* a, const uint32_t* b) {
    asm volatile(
        "mma.sync.aligned.m16n8k16.row.col.f32.bf16.bf16.f32 "
        "{%0,%1,%2,%3}, {%4,%5,%6,%7}, {%8,%9}, {%0,%1,%2,%3};"
        : "+f"(d[0]), "+f"(d[1]), "+f"(d[2]), "+f"(d[3])
        : "r"(a[0]), "r"(a[1]), "r"(a[2]), "r"(a[3]), "r"(b[0]), "r"(b[1]));
}
__device__ __forceinline__ uint32_t pack_bf16(float x, float y) {
    __nv_bfloat162 h = __floats2bfloat162_rn(x, y);
    return *(uint32_t*)&h;
}

// ---------------------------------------------------------------------------
__global__ __launch_bounds__(256)
void split_bf16(const float* __restrict__ in,
                __nv_bfloat16* __restrict__ hi,
                __nv_bfloat16* __restrict__ lo, int n)
{
    int i = (blockIdx.x * 256 + threadIdx.x) * 4;
    if (i >= n) return;
    float4 v = *(const float4*)(in + i);
    __nv_bfloat162 h0 = __floats2bfloat162_rn(v.x, v.y);
    __nv_bfloat162 h1 = __floats2bfloat162_rn(v.z, v.w);
    __nv_bfloat162 l0 = __floats2bfloat162_rn(v.x - __low2float(h0), v.y - __high2float(h0));
    __nv_bfloat162 l1 = __floats2bfloat162_rn(v.z - __low2float(h1), v.w - __high2float(h1));
    *(__nv_bfloat162*)(hi + i)     = h0;
    *(__nv_bfloat162*)(hi + i + 2) = h1;
    *(__nv_bfloat162*)(lo + i)     = l0;
    *(__nv_bfloat162*)(lo + i + 2) = l1;
}

// ---------------------------------------------------------------------------
// bf16 split GEMM: C = A B^T (+bias). Optionally writes C as bf16 hi/lo pair.
// ---------------------------------------------------------------------------
#define STRD   40
#define TILE_B (128 * STRD * 2)
#define BUF_B  (4 * TILE_B)
#define GSMEM  (2 * BUF_B)

template<bool BIAS, bool SPLIT_OUT>
__global__ __launch_bounds__(256)
void gemm_mma(const __nv_bfloat16* __restrict__ Ah, const __nv_bfloat16* __restrict__ Al,
              const __nv_bfloat16* __restrict__ Bh, const __nv_bfloat16* __restrict__ Bl,
              const float* __restrict__ bias, float* __restrict__ C,
              __nv_bfloat16* __restrict__ Ch, __nv_bfloat16* __restrict__ Cl,
              int M, int N, int K)
{
    extern __shared__ char smem[];
    const uint32_t sbase = smem_u32(smem);

    const int t    = threadIdx.x;
    const int warp = t >> 5;
    const int lane = t & 31;
    const int wm   = warp >> 2;
    const int wn   = warp & 3;
    const int bm   = blockIdx.y * 128;
    const int bn   = blockIdx.x * 128;

    const int aRow = (lane & 15);
    const int aKh  = lane >> 4;
    const int bN   = ((lane >> 4) << 3) + (lane & 7);
    const int bKh  = (lane >> 3) & 1;

    float acc[4][4][4];
    #pragma unroll
    for (int i = 0; i < 4; i++)
        #pragma unroll
        for (int j = 0; j < 4; j++)
            #pragma unroll
            for (int r = 0; r < 4; r++) acc[i][j][r] = 0.f;

    const int nck = K >> 5;

    auto load_chunk = [&](int ck, int buf) {
        const int k0 = ck << 5;
        #pragma unroll
        for (int it = 0; it < 2; it++) {
            const int linear = it * 256 + t;
            const int row = linear >> 2;
            const int kc  = (linear & 3) << 3;
            uint32_t d = sbase + buf * BUF_B + (row * STRD + kc) * 2;
            const size_t goA = (size_t)(bm + row) * K + k0 + kc;
            const size_t goB = (size_t)(bn + row) * K + k0 + kc;
            cp_async16(d,              Ah + goA);
            cp_async16(d + TILE_B,     Al + goA);
            cp_async16(d + 2 * TILE_B, Bh + goB);
            cp_async16(d + 3 * TILE_B, Bl + goB);
        }
    };

    load_chunk(0, 0);
    cp_commit();

    for (int ck = 0; ck < nck; ck++) {
        const int buf = ck & 1;
        if (ck + 1 < nck) { load_chunk(ck + 1, buf ^ 1); cp_commit(); cp_wait<1>(); }
        else              { cp_wait<0>(); }
        __syncthreads();

        const uint32_t bu  = sbase + buf * BUF_B;
        #pragma unroll
        for (int ks = 0; ks < 2; ks++) {
            const int k0 = ks * 16;
            uint32_t ah[4][4], al[4][4], bh[4][2], bl[4][2];
            #pragma unroll
            for (int mi = 0; mi < 4; mi++) {
                uint32_t off = ((wm * 64 + mi * 16 + aRow) * STRD + k0 + aKh * 8) * 2;
                ldsm_x4(ah[mi], bu + off);
                ldsm_x4(al[mi], bu + TILE_B + off);
            }
            #pragma unroll
            for (int p = 0; p < 2; p++) {
                uint32_t off = ((wn * 32 + p * 16 + bN) * STRD + k0 + bKh * 8) * 2;
                uint32_t rh[4], rl[4];
                ldsm_x4(rh, bu + 2 * TILE_B + off);
                ldsm_x4(rl, bu + 3 * TILE_B + off);
                bh[p * 2][0] = rh[0]; bh[p * 2][1] = rh[1];
                bh[p * 2 + 1][0] = rh[2]; bh[p * 2 + 1][1] = rh[3];
                bl[p * 2][0] = rl[0]; bl[p * 2][1] = rl[1];
                bl[p * 2 + 1][0] = rl[2]; bl[p * 2 + 1][1] = rl[3];
            }
            #pragma unroll
            for (int mi = 0; mi < 4; mi++)
                #pragma unroll
                for (int nj = 0; nj < 4; nj++) {
                    mma16816(acc[mi][nj], ah[mi], bh[nj]);
                    mma16816(acc[mi][nj], ah[mi], bl[nj]);
                    mma16816(acc[mi][nj], al[mi], bh[nj]);
                }
        }
        __syncthreads();
    }

    const int r0 = bm + wm * 64 + (lane >> 2);
    const int c0 = bn + wn * 32 + (lane & 3) * 2;
    #pragma unroll
    for (int mi = 0; mi < 4; mi++)
        #pragma unroll
        for (int nj = 0; nj < 4; nj++) {
            int row = r0 + mi * 16;
            int col = c0 + nj * 8;
            float2 v0 = make_float2(acc[mi][nj][0], acc[mi][nj][1]);
            float2 v1 = make_float2(acc[mi][nj][2], acc[mi][nj][3]);
            if (BIAS) {
                v0.x += bias[col]; v0.y += bias[col + 1];
                v1.x += bias[col]; v1.y += bias[col + 1];
            }
            if (SPLIT_OUT) {
                __nv_bfloat162 h0 = __floats2bfloat162_rn(v0.x, v0.y);
                __nv_bfloat162 h1 = __floats2bfloat162_rn(v1.x, v1.y);
                __nv_bfloat162 l0 = __floats2bfloat162_rn(v0.x - __low2float(h0),
                                                          v0.y - __high2float(h0));
                __nv_bfloat162 l1 = __floats2bfloat162_rn(v1.x - __low2float(h1),
                                                          v1.y - __high2float(h1));
                *(__nv_bfloat162*)(Ch + (size_t)row * N + col)       = h0;
                *(__nv_bfloat162*)(Ch + (size_t)(row + 8) * N + col) = h1;
                *(__nv_bfloat162*)(Cl + (size_t)row * N + col)       = l0;
                *(__nv_bfloat162*)(Cl + (size_t)(row + 8) * N + col) = l1;
            } else {
                *(float2*)(C + (size_t)row * N + col)       = v0;
                *(float2*)(C + (size_t)(row + 8) * N + col) = v1;
            }
        }
}

// ---------------------------------------------------------------------------
// Flash attention on mma.sync, 3-term split everywhere.
// CTA: 128 q-rows x 1 head. 8 warps, 16 q-rows each. Key blocks of 64.
// qkv layout: [4096][3072], head h: q at h*192, k at +64, v at +128.
// Output: bf16 hi/lo arrays [4096][1024] (feeds out-proj directly).
// ---------------------------------------------------------------------------
#define ATS    72                       // bf16 stride (64 + 8 pad)
#define QTILE  (128 * ATS * 2)          // 18432 B (one of Qh/Ql)
#define KVT    (64 * ATS * 2)           // 9216 B per tile
#define KVSTG  (4 * KVT)                // Kh,Kl,Vh,Vl = 36864 B per stage
#define ASMEM  (2 * KVSTG)              // 73728 B

__global__ __launch_bounds__(256)
void attn_mma(const __nv_bfloat16* __restrict__ qh,
              const __nv_bfloat16* __restrict__ ql,
              __nv_bfloat16* __restrict__ oh,
              __nv_bfloat16* __restrict__ ol)
{
    extern __shared__ char smem[];
    const uint32_t sbase = smem_u32(smem);

    const int t    = threadIdx.x;
    const int warp = t >> 5;
    const int lane = t & 31;
    const int qb   = 15 - blockIdx.x;          // big tiles first
    const int h    = blockIdx.y;
    const int b    = blockIdx.z;
    const int wr0  = warp * 16;

    const int aRow = lane & 15;
    const int aKh  = lane >> 4;
    const int bN   = ((lane >> 4) << 3) + (lane & 7);
    const int bKh  = (lane >> 3) & 1;
    // V trans-ldmatrix lane addressing
    const int vRow = ((lane >> 3) & 1) * 8 + (lane & 7);
    const int vCol = (lane >> 4) * 8;

    const size_t qrow0 = (size_t)b * SEQ + qb * 128;

    // ---- stage Q (hi/lo) and build A-fragments in registers
    #pragma unroll
    for (int it = 0; it < 4; it++) {
        const int linear = it * 256 + t;
        const int row = linear >> 3;
        const int kc  = (linear & 7) << 3;
        uint32_t d = sbase + (row * ATS + kc) * 2;
        const size_t go = (qrow0 + row) * 3072 + h * 192 + kc;
        cp_async16(d,         qh + go);
        cp_async16(d + QTILE, ql + go);
    }
    cp_commit();
    cp_wait<0>();
    __syncthreads();

    uint32_t qfh[4][4], qfl[4][4];
    #pragma unroll
    for (int kt = 0; kt < 4; kt++) {
        uint32_t off = ((wr0 + aRow) * ATS + kt * 16 + aKh * 8) * 2;
        ldsm_x4(qfh[kt], sbase + off);
        ldsm_x4(qfl[kt], sbase + QTILE + off);
    }
    __syncthreads();   // smem reused for K/V below

    float oacc[8][4];
    #pragma unroll
    for (int i = 0; i < 8; i++)
        #pragma unroll
        for (int j = 0; j < 4; j++) oacc[i][j] = 0.f;
    float m0 = -1e30f, m1 = -1e30f, l0 = 0.f, l1 = 0.f;

    const int r0g = qb * 128 + wr0 + (lane >> 2);
    const int r1g = r0g + 8;
    const int nblk = (qb + 1) * 2;

    auto load_kv = [&](int blk, int stg) {
        const int j0 = blk * 64;
        const uint32_t kb = sbase + stg * KVSTG;
        #pragma unroll
        for (int it = 0; it < 2; it++) {
            const int linear = it * 256 + t;
            const int row = linear >> 3;
            const int kc  = (linear & 7) << 3;
            uint32_t d = kb + (row * ATS + kc) * 2;
            const size_t gk = ((size_t)b * SEQ + j0 + row) * 3072 + h * 192 + 64 + kc;
            const size_t gv = gk + 64;
            cp_async16(d,           qh + gk);
            cp_async16(d + KVT,     ql + gk);
            cp_async16(d + 2 * KVT, qh + gv);
            cp_async16(d + 3 * KVT, ql + gv);
        }
    };

    load_kv(0, 0);
    cp_commit();

    for (int blk = 0; blk < nblk; blk++) {
        const int stg = blk & 1;
        const int j0  = blk * 64;
        if (blk + 1 < nblk) { load_kv(blk + 1, stg ^ 1); cp_commit(); cp_wait<1>(); }
        else                { cp_wait<0>(); }
        __syncthreads();

        const bool active = (j0 <= qb * 128 + wr0 + 15);
        if (active) {
            const uint32_t kb = sbase + stg * KVSTG;

            // ---- S = Q K^T (3-term)
            float sacc[8][4];
            #pragma unroll
            for (int i = 0; i < 8; i++)
                #pragma unroll
                for (int j = 0; j < 4; j++) sacc[i][j] = 0.f;
            #pragma unroll
            for (int kt = 0; kt < 4; kt++) {
                #pragma unroll
                for (int nt2 = 0; nt2 < 4; nt2++) {
                    uint32_t off = ((nt2 * 16 + bN) * ATS + kt * 16 + bKh * 8) * 2;
                    uint32_t rh[4], rl[4];
                    ldsm_x4(rh, kb + off);
                    ldsm_x4(rl, kb + KVT + off);
                    uint32_t kh0[2] = {rh[0], rh[1]}, kh1[2] = {rh[2], rh[3]};
                    uint32_t kl0[2] = {rl[0], rl[1]}, kl1[2] = {rl[2], rl[3]};
                    mma16816(sacc[nt2 * 2],     qfh[kt], kh0);
                    mma16816(sacc[nt2 * 2],     qfh[kt], kl0);
                    mma16816(sacc[nt2 * 2],     qfl[kt], kh0);
                    mma16816(sacc[nt2 * 2 + 1], qfh[kt], kh1);
                    mma16816(sacc[nt2 * 2 + 1], qfh[kt], kl1);
                    mma16816(sacc[nt2 * 2 + 1], qfl[kt], kh1);
                }
            }

            // ---- causal mask (only near the diagonal)
            if (j0 + 63 > qb * 128 + wr0) {
                #pragma unroll
                for (int nt = 0; nt < 8; nt++) {
                    const int c = j0 + nt * 8 + (lane & 3) * 2;
                    if (c     > r0g) sacc[nt][0] = -1e30f;
                    if (c + 1 > r0g) sacc[nt][1] = -1e30f;
                    if (c     > r1g) sacc[nt][2] = -1e30f;
                    if (c + 1 > r1g) sacc[nt][3] = -1e30f;
                }
            }

            // ---- online softmax (scale 0.125 folded into exp arg)
            float mx0 = -1e30f, mx1 = -1e30f;
            #pragma unroll
            for (int nt = 0; nt < 8; nt++) {
                mx0 = fmaxf(mx0, fmaxf(sacc[nt][0], sacc[nt][1]));
                mx1 = fmaxf(mx1, fmaxf(sacc[nt][2], sacc[nt][3]));
            }
            mx0 = fmaxf(mx0, __shfl_xor_sync(0xffffffffu, mx0, 1));
            mx0 = fmaxf(mx0, __shfl_xor_sync(0xffffffffu, mx0, 2));
            mx1 = fmaxf(mx1, __shfl_xor_sync(0xffffffffu, mx1, 1));
            mx1 = fmaxf(mx1, __shfl_xor_sync(0xffffffffu, mx1, 2));
            mx0 *= 0.125f; mx1 *= 0.125f;
            const float nm0 = fmaxf(m0, mx0), nm1 = fmaxf(m1, mx1);
            const float rs0 = __expf(m0 - nm0), rs1 = __expf(m1 - nm1);
            m0 = nm0; m1 = nm1;

            float sum0 = 0.f, sum1 = 0.f;
            #pragma unroll
            for (int nt = 0; nt < 8; nt++) {
                float p0 = __expf(fmaf(sacc[nt][0], 0.125f, -nm0));
                float p1 = __expf(fmaf(sacc[nt][1], 0.125f, -nm0));
                float p2 = __expf(fmaf(sacc[nt][2], 0.125f, -nm1));
                float p3 = __expf(fmaf(sacc[nt][3], 0.125f, -nm1));
                sacc[nt][0] = p0; sacc[nt][1] = p1;
                sacc[nt][2] = p2; sacc[nt][3] = p3;
                sum0 += p0 + p1; sum1 += p2 + p3;
            }
            sum0 += __shfl_xor_sync(0xffffffffu, sum0, 1);
            sum0 += __shfl_xor_sync(0xffffffffu, sum0, 2);
            sum1 += __shfl_xor_sync(0xffffffffu, sum1, 1);
            sum1 += __shfl_xor_sync(0xffffffffu, sum1, 2);
            l0 = l0 * rs0 + sum0;
            l1 = l1 * rs1 + sum1;

            #pragma unroll
            for (int dt = 0; dt < 8; dt++) {
                oacc[dt][0] *= rs0; oacc[dt][1] *= rs0;
                oacc[dt][2] *= rs1; oacc[dt][3] *= rs1;
            }

            // ---- O += P V (3-term), P built from sacc in registers
            #pragma unroll
            for (int kt = 0; kt < 4; kt++) {
                // V fragments for this 16-row j-chunk
                uint32_t vh[8][2], vl[8][2];
                #pragma unroll
                for (int dt2 = 0; dt2 < 4; dt2++) {
                    uint32_t off = ((kt * 16 + vRow) * ATS + dt2 * 16 + vCol) * 2;
                    uint32_t rh[4], rl[4];
                    ldsm_x4t(rh, kb + 2 * KVT + off);
                    ldsm_x4t(rl, kb + 3 * KVT + off);
                    vh[dt2 * 2][0] = rh[0]; vh[dt2 * 2][1] = rh[1];
                    vh[dt2 * 2 + 1][0] = rh[2]; vh[dt2 * 2 + 1][1] = rh[3];
                    vl[dt2 * 2][0] = rl[0]; vl[dt2 * 2][1] = rl[1];
                    vl[dt2 * 2 + 1][0] = rl[2]; vl[dt2 * 2 + 1][1] = rl[3];
                }
                // P fragments (hi/lo) for this j-chunk
                uint32_t pah[4], pal[4];
                #pragma unroll
                for (int half = 0; half < 2; half++) {
                    const float* s = sacc[kt * 2 + half];
                    __nv_bfloat162 h01 = __floats2bfloat162_rn(s[0], s[1]);
                    __nv_bfloat162 h23 = __floats2bfloat162_rn(s[2], s[3]);
                    pah[half * 2]     = *(uint32_t*)&h01;
                    pah[half * 2 + 1] = *(uint32_t*)&h23;
                    __nv_bfloat162 l01 = __floats2bfloat162_rn(
                        s[0] - __low2float(h01), s[1] - __high2float(h01));
                    __nv_bfloat162 l23 = __floats2bfloat162_rn(
                        s[2] - __low2float(h23), s[3] - __high2float(h23));
                    pal[half * 2]     = *(uint32_t*)&l01;
                    pal[half * 2 + 1] = *(uint32_t*)&l23;
                }
                // careful: A-frag order is {a0=(r,k0-7), a1=(r+8,k0-7), a2=(r,k8-15), a3=(r+8,k8-15)}
                uint32_t Ah4[4] = {pah[0], pah[1], pah[2], pah[3]};
                uint32_t Al4[4] = {pal[0], pal[1], pal[2], pal[3]};
                #pragma unroll
                for (int dt = 0; dt < 8; dt++) {
                    mma16816(oacc[dt], Ah4, vh[dt]);
                    mma16816(oacc[dt], Ah4, vl[dt]);
                    mma16816(oacc[dt], Al4, vh[dt]);
                }
            }
        }
        __syncthreads();
    }

    // ---- epilogue: normalize, split to bf16 hi/lo, store
    const float inv0 = 1.f / l0, inv1 = 1.f / l1;
    const size_t ro0 = (size_t)b * SEQ + qb * 128 + wr0 + (lane >> 2);
    const size_t ro1 = ro0 + 8;
    #pragma unroll
    for (int dt = 0; dt < 8; dt++) {
        const int col = h * 64 + dt * 8 + (lane & 3) * 2;
        float x0 = oacc[dt][0] * inv0, y0 = oacc[dt][1] * inv0;
        float x1 = oacc[dt][2] * inv1, y1 = oacc[dt][3] * inv1;
        __nv_bfloat162 h0 = __floats2bfloat162_rn(x0, y0);
        __nv_bfloat162 h1 = __floats2bfloat162_rn(x1, y1);
        __nv_bfloat162 e0 = __floats2bfloat162_rn(x0 - __low2float(h0), y0 - __high2float(h0));
        __nv_bfloat162 e1 = __floats2bfloat162_rn(x1 - __low2float(h1), y1 - __high2float(h1));
        *(__nv_bfloat162*)(oh + ro0 * EMB + col) = h0;
        *(__nv_bfloat162*)(oh + ro1 * EMB + col) = h1;
        *(__nv_bfloat162*)(ol + ro0 * EMB + col) = e0;
        *(__nv_bfloat162*)(ol + ro1 * EMB + col) = e1;
    }
}

// ---------------------------------------------------------------------------
extern "C" void kernel_launch(void* const* d_in, const int* in_sizes, int n_in,
                              void* d_out, int out_size)
{
    const float* x    = (const float*)d_in[0];
    const float* wqkv = (const float*)d_in[1];
    const float* wout = (const float*)d_in[2];
    const float* bout = (const float*)d_in[3];
    float* out = (float*)d_out;

    __nv_bfloat16 *xh, *xl, *wqh, *wql, *woh, *wol, *qkvh, *qkvl, *ath, *atl;
    cudaGetSymbolAddress((void**)&xh,   g_xh);
    cudaGetSymbolAddress((void**)&xl,   g_xl);
    cudaGetSymbolAddress((void**)&wqh,  g_wqh);
    cudaGetSymbolAddress((void**)&wql,  g_wql);
    cudaGetSymbolAddress((void**)&woh,  g_woh);
    cudaGetSymbolAddress((void**)&wol,  g_wol);
    cudaGetSymbolAddress((void**)&qkvh, g_qkvh);
    cudaGetSymbolAddress((void**)&qkvl, g_qkvl);
    cudaGetSymbolAddress((void**)&ath,  g_ath);
    cudaGetSymbolAddress((void**)&atl,  g_atl);

    cudaFuncSetAttribute(gemm_mma<false, true>,
                         cudaFuncAttributeMaxDynamicSharedMemorySize, GSMEM);
    cudaFuncSetAttribute(gemm_mma<true, false>,
                         cudaFuncAttributeMaxDynamicSharedMemorySize, GSMEM);
    cudaFuncSetAttribute(attn_mma,
                         cudaFuncAttributeMaxDynamicSharedMemorySize, ASMEM);

    split_bf16<<<(ROWS * EMB) / 1024, 256>>>(x, xh, xl, ROWS * EMB);
    split_bf16<<<(3 * EMB * EMB) / 1024, 256>>>(wqkv, wqh, wql, 3 * EMB * EMB);
    split_bf16<<<(EMB * EMB) / 1024, 256>>>(wout, woh, wol, EMB * EMB);

    // 1) QKV projection -> bf16 hi/lo directly
    gemm_mma<false, true><<<dim3(3072 / 128, ROWS / 128), 256, GSMEM>>>(
        xh, xl, wqh, wql, nullptr, nullptr, qkvh, qkvl, ROWS, 3072, EMB);

    // 2) causal flash attention on tensor cores -> bf16 hi/lo
    attn_mma<<<dim3(SEQ / 128, NH, 2), 256, ASMEM>>>(qkvh, qkvl, ath, atl);

    // 3) out projection + bias -> fp32
    gemm_mma<true, false><<<dim3(EMB / 128, ROWS / 128), 256, GSMEM>>>(
        ath, atl, woh, wol, bout, out, nullptr, nullptr, ROWS, EMB, EMB);
}